// round 1
// baseline (speedup 1.0000x reference)
#include <cuda_runtime.h>
#include <math_constants.h>

#define B_ 4
#define T_ 512
#define D_ 128
#define H_ 64
#define TT 8      // t-rows per CTA in attention kernel
#define CS 64     // s-chunk size for score phase

// Scratch: Q = input@Wt ; K' = input@Wx + demo@Wd + bh
__device__ float g_Q[B_*T_*H_];
__device__ float g_K[B_*T_*H_];

__device__ __forceinline__ float tanh_fast(float x) {
    float y;
    asm("tanh.approx.f32 %0, %1;" : "=f"(y) : "f"(x));
    return y;
}

// ---------------------------------------------------------------------------
// Kernel 1: per (b, 16-row tile) compute Q and K' rows.
// ---------------------------------------------------------------------------
__global__ __launch_bounds__(256) void prep_kernel(
    const float* __restrict__ input, const float* __restrict__ demo,
    const float* __restrict__ Wt, const float* __restrict__ Wx,
    const float* __restrict__ Wd, const float* __restrict__ bh)
{
    __shared__ float sx[16][D_];   // 8KB input tile
    const int b  = blockIdx.y;
    const int t0 = blockIdx.x * 16;
    const int tid = threadIdx.x;

    // cooperative load of 16 input rows (coalesced float4)
    {
        const float4* gin = (const float4*)(input + (size_t)(b*T_ + t0)*D_);
        float4* sx4 = (float4*)&sx[0][0];
        #pragma unroll
        for (int i = 0; i < 2; i++) sx4[tid + 256*i] = gin[tid + 256*i];
    }
    __syncthreads();

    const int h  = tid & 63;
    const int tg = tid >> 6;     // 0..3

    float dd = bh[h];
    #pragma unroll
    for (int j = 0; j < 12; j++) dd = fmaf(demo[b*12 + j], Wd[j*H_ + h], dd);

    float aq[4] = {0.f,0.f,0.f,0.f};
    float ak[4] = {0.f,0.f,0.f,0.f};
    #pragma unroll 4
    for (int d = 0; d < D_; d++) {
        float wt = Wt[d*H_ + h];
        float wx = Wx[d*H_ + h];
        #pragma unroll
        for (int i = 0; i < 4; i++) {
            float x = sx[tg + 4*i][d];
            aq[i] = fmaf(x, wt, aq[i]);
            ak[i] = fmaf(x, wx, ak[i]);
        }
    }
    #pragma unroll
    for (int i = 0; i < 4; i++) {
        int t = t0 + tg + 4*i;
        g_Q[(size_t)(b*T_ + t)*H_ + h] = aq[i];
        g_K[(size_t)(b*T_ + t)*H_ + h] = ak[i] + dd;
    }
}

// ---------------------------------------------------------------------------
// Kernel 2: per (b, TT-row tile): scores -> softmax(exp-before-mask) -> P@input
// ---------------------------------------------------------------------------
__global__ __launch_bounds__(256) void attn_kernel(
    const float* __restrict__ input,
    const float* __restrict__ Wa, const float* __restrict__ ba,
    float* __restrict__ out_v, float* __restrict__ out_e)
{
    __shared__ float sQ[TT][H_];       // 2 KB
    __shared__ float sKT[H_][CS + 1];  // ~16.6 KB, transposed K' chunk (padded)
    __shared__ float sSc[TT][T_];      // 16 KB score rows
    __shared__ float sWa[H_];

    const int b   = blockIdx.y;
    const int t0  = blockIdx.x * TT;
    const int tid = threadIdx.x;

    // load Q tile + Wa
    {
        const float4* gq = (const float4*)(g_Q + (size_t)(b*T_ + t0)*H_);
        if (tid < TT*H_/4) ((float4*)sQ)[tid] = gq[tid];
        if (tid < H_) sWa[tid] = Wa[tid];
    }
    const float bav = ba[0];

    const int sl = tid & 63;   // s within chunk
    const int tg = tid >> 6;   // 0..3

    // ---- score phase: e[t][s] = ba + sum_h Wa[h]*tanh(Q[t][h] + K'[s][h]) ----
    for (int c = 0; c < T_/CS; c++) {
        __syncthreads();  // protect previous chunk reads (and initial sQ/sWa loads)
        {
            // load + transpose K' chunk: read coalesced over h, write padded rows
            const float* kp = g_K + (size_t)(b*T_ + c*CS)*H_;
            const int hh = tid & 63;
            const int sb = tid >> 6;
            #pragma unroll
            for (int i = 0; i < CS/4; i++) {
                int si = sb + 4*i;
                sKT[hh][si] = kp[(size_t)si*H_ + hh];
            }
        }
        __syncthreads();

        #pragma unroll
        for (int r = 0; r < TT/4; r++) {
            const int t = tg + 4*r;
            float acc = bav;
            #pragma unroll
            for (int h4 = 0; h4 < H_/4; h4++) {
                float4 q = ((const float4*)sQ[t])[h4];
                float4 w = ((const float4*)sWa)[h4];
                float k0 = sKT[4*h4+0][sl];
                float k1 = sKT[4*h4+1][sl];
                float k2 = sKT[4*h4+2][sl];
                float k3 = sKT[4*h4+3][sl];
                acc = fmaf(w.x, tanh_fast(q.x + k0), acc);
                acc = fmaf(w.y, tanh_fast(q.y + k1), acc);
                acc = fmaf(w.z, tanh_fast(q.z + k2), acc);
                acc = fmaf(w.w, tanh_fast(q.w + k3), acc);
            }
            sSc[t][c*CS + sl] = acc;
        }
    }
    __syncthreads();

    // ---- softmax: warp w owns row w. max over FULL row, exp, THEN mask s<=t ----
    {
        const int w    = tid >> 5;
        const int lane = tid & 31;
        const int t    = t0 + w;
        float* row = sSc[w];
        float vals[T_/32];
        float m = -CUDART_INF_F;
        #pragma unroll
        for (int i = 0; i < T_/32; i++) {
            vals[i] = row[lane + 32*i];
            m = fmaxf(m, vals[i]);
        }
        #pragma unroll
        for (int off = 16; off; off >>= 1) m = fmaxf(m, __shfl_xor_sync(0xffffffffu, m, off));
        float sum = 0.f;
        #pragma unroll
        for (int i = 0; i < T_/32; i++) {
            int s = lane + 32*i;
            float e = __expf(vals[i] - m);
            if (s > t) e = 0.f;          // causal mask AFTER exp
            vals[i] = e;
            sum += e;
        }
        #pragma unroll
        for (int off = 16; off; off >>= 1) sum += __shfl_xor_sync(0xffffffffu, sum, off);
        float inv = 1.f / (sum + 1e-7f);
        float* ge = out_e + ((size_t)(b*T_ + t))*T_;
        #pragma unroll
        for (int i = 0; i < T_/32; i++) {
            int s = lane + 32*i;
            float p = vals[i] * inv;
            row[s] = p;     // reuse for v phase
            ge[s]  = p;     // coalesced global write
        }
    }

    // ---- v phase: v[t][:] = sum_s P[t][s] * input[b][s][:] ----
    {
        const int tl = tid >> 5;        // warp -> t row (TT==8 warps)
        const int d4 = tid & 31;        // float4 column
        float4 acc = make_float4(0.f, 0.f, 0.f, 0.f);
        float* sIn = &sKT[0][0];        // reuse as 32x128 float staging (16KB)
        for (int c = 0; c < T_/32; c++) {
            __syncthreads();            // protect previous chunk / score-phase reads
            const float4* gin = (const float4*)(input + (size_t)(b*T_ + c*32)*D_);
            #pragma unroll
            for (int i = 0; i < 4; i++) ((float4*)sIn)[tid + 256*i] = gin[tid + 256*i];
            __syncthreads();
            #pragma unroll
            for (int s = 0; s < 32; s++) {
                float p = sSc[tl][c*32 + s];
                float4 x = ((const float4*)(sIn + s*D_))[d4];
                acc.x = fmaf(p, x.x, acc.x);
                acc.y = fmaf(p, x.y, acc.y);
                acc.z = fmaf(p, x.z, acc.z);
                acc.w = fmaf(p, x.w, acc.w);
            }
        }
        float4* gv = (float4*)(out_v + (size_t)(b*T_ + t0 + tl)*D_);
        gv[d4] = acc;
    }
}

// ---------------------------------------------------------------------------
extern "C" void kernel_launch(void* const* d_in, const int* in_sizes, int n_in,
                              void* d_out, int out_size)
{
    const float* input = (const float*)d_in[0];
    const float* demo  = (const float*)d_in[1];
    const float* Wt    = (const float*)d_in[2];
    const float* Wx    = (const float*)d_in[3];
    const float* Wd    = (const float*)d_in[4];
    const float* bh    = (const float*)d_in[5];
    const float* Wa    = (const float*)d_in[6];
    const float* ba    = (const float*)d_in[7];

    float* out_v = (float*)d_out;                       // [B,T,D]
    float* out_e = out_v + (size_t)B_ * T_ * D_;        // [B,T,T]

    dim3 g1(T_/16, B_);
    prep_kernel<<<g1, 256>>>(input, demo, Wt, Wx, Wd, bh);

    dim3 g2(T_/TT, B_);
    attn_kernel<<<g2, 256>>>(input, Wa, ba, out_v, out_e);
}

// round 2
// speedup vs baseline: 1.0557x; 1.0557x over previous
#include <cuda_runtime.h>
#include <math_constants.h>

#define B_ 4
#define T_ 512
#define D_ 128
#define H_ 64
#define TT 8      // t-rows per CTA in attention kernel
#define CS 64     // s-chunk size for score phase
#define KP (H_ + 4)   // padded K row stride (68 floats -> conflict-free f4 reads)

// Scratch: Q = input@Wt ; K' = input@Wx + demo@Wd + bh
__device__ float g_Q[B_*T_*H_];
__device__ float g_K[B_*T_*H_];

__device__ __forceinline__ float tanh_fast(float x) {
    float y;
    asm("tanh.approx.f32 %0, %1;" : "=f"(y) : "f"(x));
    return y;
}

// ---------------------------------------------------------------------------
// Kernel 1: per (b, 16-row tile) compute Q and K' rows.
// ---------------------------------------------------------------------------
__global__ __launch_bounds__(256) void prep_kernel(
    const float* __restrict__ input, const float* __restrict__ demo,
    const float* __restrict__ Wt, const float* __restrict__ Wx,
    const float* __restrict__ Wd, const float* __restrict__ bh)
{
    __shared__ float sx[16][D_];   // 8KB input tile
    const int b  = blockIdx.y;
    const int t0 = blockIdx.x * 16;
    const int tid = threadIdx.x;

    {
        const float4* gin = (const float4*)(input + (size_t)(b*T_ + t0)*D_);
        float4* sx4 = (float4*)&sx[0][0];
        #pragma unroll
        for (int i = 0; i < 2; i++) sx4[tid + 256*i] = gin[tid + 256*i];
    }
    __syncthreads();

    const int h  = tid & 63;
    const int tg = tid >> 6;     // 0..3

    float dd = bh[h];
    #pragma unroll
    for (int j = 0; j < 12; j++) dd = fmaf(demo[b*12 + j], Wd[j*H_ + h], dd);

    float aq[4] = {0.f,0.f,0.f,0.f};
    float ak[4] = {0.f,0.f,0.f,0.f};
    #pragma unroll 4
    for (int d = 0; d < D_; d++) {
        float wt = Wt[d*H_ + h];
        float wx = Wx[d*H_ + h];
        #pragma unroll
        for (int i = 0; i < 4; i++) {
            float x = sx[tg + 4*i][d];
            aq[i] = fmaf(x, wt, aq[i]);
            ak[i] = fmaf(x, wx, ak[i]);
        }
    }
    #pragma unroll
    for (int i = 0; i < 4; i++) {
        int t = t0 + tg + 4*i;
        g_Q[(size_t)(b*T_ + t)*H_ + h] = aq[i];
        g_K[(size_t)(b*T_ + t)*H_ + h] = ak[i] + dd;
    }
}

// ---------------------------------------------------------------------------
// Kernel 2: per (b, TT-row tile): scores -> softmax(exp-before-mask) -> P@input
// 2 CTAs/SM via launch_bounds; padded natural-layout K chunk; 4 acc chains.
// ---------------------------------------------------------------------------
__global__ __launch_bounds__(256, 2) void attn_kernel(
    const float* __restrict__ input,
    const float* __restrict__ Wa, const float* __restrict__ ba,
    float* __restrict__ out_v, float* __restrict__ out_e)
{
    __shared__ float sQ[TT][H_];       // 2 KB
    __shared__ float sK[CS][KP];       // 17 KB, natural [s][h] layout, padded
    __shared__ float sSc[TT][T_];      // 16 KB score rows
    __shared__ float sWa[H_];

    const int b   = blockIdx.y;
    const int t0  = blockIdx.x * TT;
    const int tid = threadIdx.x;

    // load Q tile + Wa
    {
        const float4* gq = (const float4*)(g_Q + (size_t)(b*T_ + t0)*H_);
        if (tid < TT*H_/4) ((float4*)sQ)[tid] = gq[tid];
        if (tid < H_) sWa[tid] = Wa[tid];
    }
    const float bav = ba[0];

    const int sl = tid & 63;   // s within chunk
    const int tg = tid >> 6;   // 0..3

    // ---- score phase: e[t][s] = ba + sum_h Wa[h]*tanh(Q[t][h] + K'[s][h]) ----
    for (int c = 0; c < T_/CS; c++) {
        __syncthreads();  // protect previous chunk reads (and initial sQ/sWa loads)
        {
            // straight float4 copy of 64 K' rows into padded smem rows
            const float4* kp = (const float4*)(g_K + (size_t)(b*T_ + c*CS)*H_);
            const int j = tid & 15;          // float4 within row
            const int r0 = tid >> 4;         // 16 rows per pass
            #pragma unroll
            for (int i = 0; i < 4; i++) {
                int r = r0 + 16*i;
                *(float4*)&sK[r][4*j] = kp[(size_t)r*16 + j];
            }
        }
        __syncthreads();

        #pragma unroll
        for (int r = 0; r < TT/4; r++) {
            const int t = tg + 4*r;
            float a0 = 0.f, a1 = 0.f, a2 = 0.f, a3 = 0.f;
            #pragma unroll
            for (int h4 = 0; h4 < H_/4; h4++) {
                float4 q = ((const float4*)sQ[t])[h4];
                float4 w = ((const float4*)sWa)[h4];
                float4 k = *(const float4*)&sK[sl][4*h4];
                a0 = fmaf(w.x, tanh_fast(q.x + k.x), a0);
                a1 = fmaf(w.y, tanh_fast(q.y + k.y), a1);
                a2 = fmaf(w.z, tanh_fast(q.z + k.z), a2);
                a3 = fmaf(w.w, tanh_fast(q.w + k.w), a3);
            }
            sSc[t][c*CS + sl] = bav + ((a0 + a1) + (a2 + a3));
        }
    }
    __syncthreads();

    // ---- softmax: warp w owns row w. max over FULL row, exp, THEN mask s<=t ----
    {
        const int w    = tid >> 5;
        const int lane = tid & 31;
        const int t    = t0 + w;
        float* row = sSc[w];
        float vals[T_/32];
        float m = -CUDART_INF_F;
        #pragma unroll
        for (int i = 0; i < T_/32; i++) {
            vals[i] = row[lane + 32*i];
            m = fmaxf(m, vals[i]);
        }
        #pragma unroll
        for (int off = 16; off; off >>= 1) m = fmaxf(m, __shfl_xor_sync(0xffffffffu, m, off));
        float sum = 0.f;
        #pragma unroll
        for (int i = 0; i < T_/32; i++) {
            int s = lane + 32*i;
            float e = __expf(vals[i] - m);
            if (s > t) e = 0.f;          // causal mask AFTER exp
            vals[i] = e;
            sum += e;
        }
        #pragma unroll
        for (int off = 16; off; off >>= 1) sum += __shfl_xor_sync(0xffffffffu, sum, off);
        float inv = 1.f / (sum + 1e-7f);
        float* ge = out_e + ((size_t)(b*T_ + t))*T_;
        #pragma unroll
        for (int i = 0; i < T_/32; i++) {
            int s = lane + 32*i;
            float p = vals[i] * inv;
            row[s] = p;     // reuse for v phase
            ge[s]  = p;     // coalesced global write
        }
    }

    // ---- v phase: v[t][:] = sum_s P[t][s] * input[b][s][:] ----
    {
        const int tl = tid >> 5;        // warp -> t row (TT==8 warps)
        const int d4 = tid & 31;        // float4 column
        float4 acc = make_float4(0.f, 0.f, 0.f, 0.f);
        float* sIn = &sK[0][0];         // reuse as 32x128 float staging (16KB)
        for (int c = 0; c < T_/32; c++) {
            __syncthreads();            // protect previous chunk / score-phase reads
            const float4* gin = (const float4*)(input + (size_t)(b*T_ + c*32)*D_);
            #pragma unroll
            for (int i = 0; i < 4; i++) ((float4*)sIn)[tid + 256*i] = gin[tid + 256*i];
            __syncthreads();
            #pragma unroll
            for (int s = 0; s < 32; s++) {
                float p = sSc[tl][c*32 + s];
                float4 x = ((const float4*)(sIn + s*D_))[d4];
                acc.x = fmaf(p, x.x, acc.x);
                acc.y = fmaf(p, x.y, acc.y);
                acc.z = fmaf(p, x.z, acc.z);
                acc.w = fmaf(p, x.w, acc.w);
            }
        }
        float4* gv = (float4*)(out_v + (size_t)(b*T_ + t0 + tl)*D_);
        gv[d4] = acc;
    }
}

// ---------------------------------------------------------------------------
extern "C" void kernel_launch(void* const* d_in, const int* in_sizes, int n_in,
                              void* d_out, int out_size)
{
    const float* input = (const float*)d_in[0];
    const float* demo  = (const float*)d_in[1];
    const float* Wt    = (const float*)d_in[2];
    const float* Wx    = (const float*)d_in[3];
    const float* Wd    = (const float*)d_in[4];
    const float* bh    = (const float*)d_in[5];
    const float* Wa    = (const float*)d_in[6];
    const float* ba    = (const float*)d_in[7];

    float* out_v = (float*)d_out;                       // [B,T,D]
    float* out_e = out_v + (size_t)B_ * T_ * D_;        // [B,T,T]

    dim3 g1(T_/16, B_);
    prep_kernel<<<g1, 256>>>(input, demo, Wt, Wx, Wd, bh);

    dim3 g2(T_/TT, B_);
    attn_kernel<<<g2, 256>>>(input, Wa, ba, out_v, out_e);
}